// round 6
// baseline (speedup 1.0000x reference)
#include <cuda_runtime.h>
#include <cuda_fp16.h>
#include <cstdint>
#include <cstddef>

// ============================================================================
// W8Linear, base sm_103 target (no tcgen05 at this PTX target -> mma.sync HMMA).
//   Y = fp16( fp32(X @ dequant(Wq)^T) * scale + bias ),  M=8192, K=4096, N=11008
// Harness dtype contract (hypothesis): x/scale/bias = float32, qweight = int32,
// output = float32. Convert to fp16 in registers while staging to SMEM.
// Tile M128 x N256 x K64, 512 thr (16 warps, 4x4, warp tile 32x64).
// Barrier-separated loop, single A / single B buffer, X register prefetch.
// ============================================================================

#define BM 128
#define BN 256
#define BK 64
#define KSTEPS 64          // 4096 / 64
#define INF 4096
#define OUTF 11008
#define THREADS 512

// SMEM layout (bytes)
#define SM_SC 0                       // 256 fp16 scale
#define SM_BI 512                     // 256 fp16 bias
#define SM_A  1024                    // 16384: 128 rows x 128B (SW128), fp16
#define SM_B  (1024 + 16384)          // 32768: 256 rows x 128B (SW128), fp16
#define SM_TOTAL (SM_B + 32768)       // 50176

__device__ __forceinline__ uint32_t swz(uint32_t o) { return o ^ ((o >> 3) & 0x70); }

__device__ __forceinline__ uint32_t s2u(const void* p) {
    return (uint32_t)__cvta_generic_to_shared(p);
}

__device__ __forceinline__ void sts64(uint32_t a, uint32_t x, uint32_t y) {
    asm volatile("st.shared.v2.b32 [%0], {%1,%2};" :: "r"(a), "r"(x), "r"(y) : "memory");
}

__device__ __forceinline__ void ldsm4(uint32_t (&r)[4], uint32_t a) {
    asm volatile("ldmatrix.sync.aligned.m8n8.x4.shared.b16 {%0,%1,%2,%3}, [%4];"
                 : "=r"(r[0]), "=r"(r[1]), "=r"(r[2]), "=r"(r[3]) : "r"(a));
}

__device__ __forceinline__ void mma16816(float (&d)[4], const uint32_t (&a)[4],
                                         uint32_t b0, uint32_t b1) {
    asm volatile("mma.sync.aligned.m16n8k16.row.col.f32.f16.f16.f32 "
                 "{%0,%1,%2,%3}, {%4,%5,%6,%7}, {%8,%9}, {%0,%1,%2,%3};"
                 : "+f"(d[0]), "+f"(d[1]), "+f"(d[2]), "+f"(d[3])
                 : "r"(a[0]), "r"(a[1]), "r"(a[2]), "r"(a[3]),
                   "r"(b0), "r"(b1));
}

__device__ __forceinline__ uint32_t h2u(__half2 h) {
    return *reinterpret_cast<uint32_t*>(&h);
}

__global__ void __launch_bounds__(THREADS)
w8lin_kernel(const float* __restrict__ X, const int* __restrict__ Wq,
             const float* __restrict__ scale, const float* __restrict__ bias,
             float* __restrict__ Y)
{
    extern __shared__ char smem[];
    const uint32_t sb = s2u(smem);
    const int tid = threadIdx.x;
    const int wid = tid >> 5;
    const int lid = tid & 31;
    const int n0 = blockIdx.x * BN;
    const int m0 = blockIdx.y * BM;
    const int m_off = (wid & 3) * 32;   // 4 M-warp groups
    const int n_off = (wid >> 2) * 64;  // 4 N-warp groups

    if (tid < 256) {
        ((__half*)(smem + SM_SC))[tid] = __float2half_rn(scale[n0 + tid]);
        ((__half*)(smem + SM_BI))[tid] = __float2half_rn(bias[n0 + tid]);
    }

    // ---- per-thread ldmatrix byte offsets (pre-swizzle; +kk*32 per k-step) ----
    uint32_t arow[2], brow[4];
    #pragma unroll
    for (int i = 0; i < 2; i++)
        arow[i] = (uint32_t)((m_off + i * 16 + (lid & 15)) * 128 + (lid >> 4) * 16);
    #pragma unroll
    for (int j = 0; j < 4; j++)
        brow[j] = (uint32_t)((n_off + j * 16 + ((lid >> 4) & 1) * 8 + (lid & 7)) * 128
                             + ((lid >> 3) & 1) * 16);

    float acc[2][8][4];
    #pragma unroll
    for (int i = 0; i < 2; i++)
        #pragma unroll
        for (int j = 0; j < 8; j++)
            #pragma unroll
            for (int q = 0; q < 4; q++) acc[i][j][q] = 0.0f;

    // ---- X prefetch: 128 rows x 64 floats per step; 4 x float4 per thread ----
    float4 xreg[4];
    auto ldgX = [&](int s) {
        const float* g = X + (size_t)m0 * INF + (size_t)s * BK;
        #pragma unroll
        for (int i = 0; i < 4; i++) {
            int idx = tid + i * THREADS;           // 2048 chunks
            int r = idx >> 4, c = idx & 15;        // 16 x 4-float chunks per row
            xreg[i] = *(const float4*)(g + (size_t)r * INF + c * 4);
        }
    };
    auto stsX = [&]() {
        #pragma unroll
        for (int i = 0; i < 4; i++) {
            int idx = tid + i * THREADS;
            int r = idx >> 4, c = idx & 15;
            uint32_t h01 = h2u(__floats2half2_rn(xreg[i].x, xreg[i].y));
            uint32_t h23 = h2u(__floats2half2_rn(xreg[i].z, xreg[i].w));
            sts64(sb + SM_A + swz((uint32_t)(r * 128 + c * 8)), h01, h23);
        }
    };
    // ---- W: 256 rows x 64 int32 per step; 8 x int4 per thread (transient) ----
    auto loadW = [&](int s) {
        const int* g = Wq + (size_t)n0 * INF + (size_t)s * BK;
        int4 w[8];
        #pragma unroll
        for (int p = 0; p < 8; p++) {
            int idx = tid + p * THREADS;           // 4096 chunks
            int r = idx >> 4, c = idx & 15;
            w[p] = *(const int4*)(g + (size_t)r * INF + c * 4);
        }
        #pragma unroll
        for (int p = 0; p < 8; p++) {
            int idx = tid + p * THREADS;
            int r = idx >> 4, c = idx & 15;
            uint32_t h01 = h2u(__halves2half2(__int2half_rn(w[p].x),
                                              __int2half_rn(w[p].y)));
            uint32_t h23 = h2u(__halves2half2(__int2half_rn(w[p].z),
                                              __int2half_rn(w[p].w)));
            sts64(sb + SM_B + swz((uint32_t)(r * 128 + c * 8)), h01, h23);
        }
    };

    auto compute = [&]() {
        #pragma unroll
        for (int kk = 0; kk < 4; kk++) {
            uint32_t a[2][4], b[4][4];
            #pragma unroll
            for (int i = 0; i < 2; i++) ldsm4(a[i], sb + SM_A + swz(arow[i] + kk * 32));
            #pragma unroll
            for (int j = 0; j < 4; j++) ldsm4(b[j], sb + SM_B + swz(brow[j] + kk * 32));
            #pragma unroll
            for (int i = 0; i < 2; i++)
                #pragma unroll
                for (int j = 0; j < 4; j++) {
                    mma16816(acc[i][2 * j],     a[i], b[j][0], b[j][1]);
                    mma16816(acc[i][2 * j + 1], a[i], b[j][2], b[j][3]);
                }
        }
    };

    // ---- prologue ----
    ldgX(0);

    // ---- mainloop: every SMEM hazard edge crosses a __syncthreads() ----
    for (int s = 0; s < KSTEPS; s++) {
        stsX();                            // A <- fp16(X(s))   (regs from prev iter)
        if (s + 1 < KSTEPS) ldgX(s + 1);   // prefetch X(s+1)
        loadW(s);                          // B <- fp16(W(s))   (LDG+cvt+STS)
        __syncthreads();                   // staging visible to all warps
        compute();
        __syncthreads();                   // all warps done reading A and B
    }

    // ---- epilogue: fp32 acc -> fp16 round -> *scale + bias (fp16) -> f32 out ----
    const int gid = lid >> 2, tig = lid & 3;
    #pragma unroll
    for (int i = 0; i < 2; i++) {
        const int rbase = m0 + m_off + i * 16 + gid;
        #pragma unroll
        for (int j = 0; j < 8; j++) {
            const int cl = n_off + j * 8 + tig * 2;       // local col (even)
            __half2 sc = *(const __half2*)(smem + SM_SC + cl * 2);
            __half2 bi = *(const __half2*)(smem + SM_BI + cl * 2);
            __half2 h01 = __floats2half2_rn(acc[i][j][0], acc[i][j][1]);
            __half2 h23 = __floats2half2_rn(acc[i][j][2], acc[i][j][3]);
            __half2 r01 = __hadd2(__hmul2(h01, sc), bi);
            __half2 r23 = __hadd2(__hmul2(h23, sc), bi);
            *(float2*)(Y + (size_t)rbase * OUTF + n0 + cl) =
                make_float2(__low2float(r01), __high2float(r01));
            *(float2*)(Y + (size_t)(rbase + 8) * OUTF + n0 + cl) =
                make_float2(__low2float(r23), __high2float(r23));
        }
    }
}

extern "C" void kernel_launch(void* const* d_in, const int* in_sizes, int n_in,
                              void* d_out, int out_size) {
    const float* X  = (const float*)d_in[0];
    const int*   Wq = (const int*)d_in[1];
    const float* sc = (const float*)d_in[2];
    const float* bi = (const float*)d_in[3];
    float* Y = (float*)d_out;

    cudaFuncSetAttribute(w8lin_kernel,
                         cudaFuncAttributeMaxDynamicSharedMemorySize, SM_TOTAL);
    dim3 grid(OUTF / BN, 8192 / BM);   // (43, 64)
    w8lin_kernel<<<grid, THREADS, SM_TOTAL>>>(X, Wq, sc, bi, Y);
}

// round 7
// speedup vs baseline: 2.1465x; 2.1465x over previous
#include <cuda_runtime.h>
#include <cuda_fp16.h>
#include <cstdint>
#include <cstddef>

// ============================================================================
// W8Linear (harness dtypes: X f32, Wq i32, scale/bias f32, out f32).
//   Y = fp16( fp32(X @ W^T) * scale + bias ),  M=8192, K=4096, N=11008.
// Phase 1: convert W->fp16, X->fp16 into __device__ scratch (one pass).
// Phase 2: pipelined HMMA GEMM, M128 x N256 x K64 tiles, 512 thr,
//          4-stage cp.async ring, ldmatrix + mma.sync.m16n8k16, fp32 accum.
// ============================================================================

#define BM 128
#define BN 256
#define BK 64
#define KSTEPS 64
#define INF 4096
#define OUTF 11008
#define MROWS 8192
#define THREADS 512
#define STAGES 4

// SMEM layout (bytes)
#define ASTAGE 16384
#define BSTAGE 32768
#define SM_A  0
#define SM_B  (STAGES * ASTAGE)                   // 65536
#define SM_SC (SM_B + STAGES * BSTAGE)            // 196608
#define SM_BI (SM_SC + 512)
#define SM_TOTAL (SM_BI + 512)                    // 197632

// fp16 scratch (module-static device memory; not a runtime allocation)
__device__ __align__(16) __half g_Wh[(size_t)OUTF * INF];
__device__ __align__(16) __half g_Xh[(size_t)MROWS * INF];

__device__ __forceinline__ uint32_t swz(uint32_t o) { return o ^ ((o >> 3) & 0x70); }

__device__ __forceinline__ uint32_t s2u(const void* p) {
    return (uint32_t)__cvta_generic_to_shared(p);
}

__device__ __forceinline__ void cp16(uint32_t s, const void* g) {
    asm volatile("cp.async.cg.shared.global [%0], [%1], 16;" :: "r"(s), "l"(g));
}
#define CP_COMMIT() asm volatile("cp.async.commit_group;" ::: "memory")
#define CP_WAIT2()  asm volatile("cp.async.wait_group 2;" ::: "memory")

__device__ __forceinline__ void ldsm4(uint32_t (&r)[4], uint32_t a) {
    asm volatile("ldmatrix.sync.aligned.m8n8.x4.shared.b16 {%0,%1,%2,%3}, [%4];"
                 : "=r"(r[0]), "=r"(r[1]), "=r"(r[2]), "=r"(r[3]) : "r"(a));
}

__device__ __forceinline__ void mma16816(float (&d)[4], const uint32_t (&a)[4],
                                         uint32_t b0, uint32_t b1) {
    asm volatile("mma.sync.aligned.m16n8k16.row.col.f32.f16.f16.f32 "
                 "{%0,%1,%2,%3}, {%4,%5,%6,%7}, {%8,%9}, {%0,%1,%2,%3};"
                 : "+f"(d[0]), "+f"(d[1]), "+f"(d[2]), "+f"(d[3])
                 : "r"(a[0]), "r"(a[1]), "r"(a[2]), "r"(a[3]),
                   "r"(b0), "r"(b1));
}

__device__ __forceinline__ uint32_t h2u(__half2 h) {
    return *reinterpret_cast<uint32_t*>(&h);
}

// ---- Phase 1 kernels ----
__global__ void __launch_bounds__(256) cvtW_kernel(const int4* __restrict__ w,
                                                   uint2* __restrict__ o) {
    size_t i = (size_t)blockIdx.x * 256 + threadIdx.x;
    int4 v = w[i];
    uint2 r;
    r.x = h2u(__halves2half2(__int2half_rn(v.x), __int2half_rn(v.y)));
    r.y = h2u(__halves2half2(__int2half_rn(v.z), __int2half_rn(v.w)));
    o[i] = r;
}
__global__ void __launch_bounds__(256) cvtX_kernel(const float4* __restrict__ x,
                                                   uint2* __restrict__ o) {
    size_t i = (size_t)blockIdx.x * 256 + threadIdx.x;
    float4 v = x[i];
    uint2 r;
    r.x = h2u(__floats2half2_rn(v.x, v.y));
    r.y = h2u(__floats2half2_rn(v.z, v.w));
    o[i] = r;
}

// ---- Phase 2: GEMM ----
__global__ void __launch_bounds__(THREADS)
w8lin_kernel(const float* __restrict__ scale, const float* __restrict__ bias,
             float* __restrict__ Y)
{
    extern __shared__ char smem[];
    const uint32_t sb = s2u(smem);
    const int tid = threadIdx.x;
    const int wid = tid >> 5;
    const int lid = tid & 31;
    const int n0 = blockIdx.x * BN;
    const int m0 = blockIdx.y * BM;
    const int m_off = (wid & 3) * 32;   // 4 M-warp groups
    const int n_off = (wid >> 2) * 64;  // 4 N-warp groups

    if (tid < 256) {
        ((__half*)(smem + SM_SC))[tid] = __float2half_rn(scale[n0 + tid]);
        ((__half*)(smem + SM_BI))[tid] = __float2half_rn(bias[n0 + tid]);
    }

    // ---- stage loaders (cp.async, SW128 rows of 128B) ----
    auto loadA = [&](int s, int stg) {
        uint32_t base = sb + SM_A + (uint32_t)stg * ASTAGE;
        const __half* g = g_Xh + (size_t)m0 * INF + (size_t)s * BK;
        #pragma unroll
        for (int i = 0; i < 2; i++) {
            int idx = tid + i * THREADS;          // 1024 16B chunks
            int r = idx >> 3, c = idx & 7;
            cp16(base + swz((uint32_t)(r * 128 + c * 16)),
                 g + (size_t)r * INF + c * 8);
        }
    };
    auto loadB = [&](int s, int stg) {
        uint32_t base = sb + SM_B + (uint32_t)stg * BSTAGE;
        const __half* g = g_Wh + (size_t)n0 * INF + (size_t)s * BK;
        #pragma unroll
        for (int i = 0; i < 4; i++) {
            int idx = tid + i * THREADS;          // 2048 16B chunks
            int r = idx >> 3, c = idx & 7;
            cp16(base + swz((uint32_t)(r * 128 + c * 16)),
                 g + (size_t)r * INF + c * 8);
        }
    };

    // ---- per-thread ldmatrix byte offsets (pre-swizzle; +kk*32 per k-step) ----
    uint32_t arow[2], brow[4];
    #pragma unroll
    for (int i = 0; i < 2; i++)
        arow[i] = (uint32_t)((m_off + i * 16 + (lid & 15)) * 128 + (lid >> 4) * 16);
    #pragma unroll
    for (int j = 0; j < 4; j++)
        brow[j] = (uint32_t)((n_off + j * 16 + ((lid >> 4) & 1) * 8 + (lid & 7)) * 128
                             + ((lid >> 3) & 1) * 16);

    float acc[2][8][4];
    #pragma unroll
    for (int i = 0; i < 2; i++)
        #pragma unroll
        for (int j = 0; j < 8; j++)
            #pragma unroll
            for (int q = 0; q < 4; q++) acc[i][j][q] = 0.0f;

    auto compute = [&](int stg) {
        uint32_t Ab = sb + SM_A + (uint32_t)stg * ASTAGE;
        uint32_t Bb = sb + SM_B + (uint32_t)stg * BSTAGE;
        #pragma unroll
        for (int kk = 0; kk < 4; kk++) {
            uint32_t a[2][4], b[4][4];
            #pragma unroll
            for (int i = 0; i < 2; i++) ldsm4(a[i], Ab + swz(arow[i] + kk * 32));
            #pragma unroll
            for (int j = 0; j < 4; j++) ldsm4(b[j], Bb + swz(brow[j] + kk * 32));
            #pragma unroll
            for (int i = 0; i < 2; i++)
                #pragma unroll
                for (int j = 0; j < 4; j++) {
                    mma16816(acc[i][2 * j],     a[i], b[j][0], b[j][1]);
                    mma16816(acc[i][2 * j + 1], a[i], b[j][2], b[j][3]);
                }
        }
    };

    // ---- prologue: fill 3 stages ----
    #pragma unroll
    for (int s = 0; s < 3; s++) {
        loadA(s, s); loadB(s, s); CP_COMMIT();
    }

    // ---- mainloop: one barrier per iter ----
    for (int s = 0; s < KSTEPS; s++) {
        CP_WAIT2();                 // my chunks of group s complete
        __syncthreads();            // -> all warps' chunks of stage s complete
        compute(s & 3);
        if (s + 3 < KSTEPS) {       // refill stage (s+3)&3 == (s-1)&3 (consumed)
            loadA(s + 3, (s + 3) & 3);
            loadB(s + 3, (s + 3) & 3);
        }
        CP_COMMIT();                // keep group accounting invariant
    }

    // ---- epilogue: fp32 acc -> fp16 round -> *scale + bias (fp16) -> f32 out ----
    const int gid = lid >> 2, tig = lid & 3;
    #pragma unroll
    for (int i = 0; i < 2; i++) {
        const int rbase = m0 + m_off + i * 16 + gid;
        #pragma unroll
        for (int j = 0; j < 8; j++) {
            const int cl = n_off + j * 8 + tig * 2;
            __half2 sc = *(const __half2*)(smem + SM_SC + cl * 2);
            __half2 bi = *(const __half2*)(smem + SM_BI + cl * 2);
            __half2 h01 = __floats2half2_rn(acc[i][j][0], acc[i][j][1]);
            __half2 h23 = __floats2half2_rn(acc[i][j][2], acc[i][j][3]);
            __half2 r01 = __hadd2(__hmul2(h01, sc), bi);
            __half2 r23 = __hadd2(__hmul2(h23, sc), bi);
            *(float2*)(Y + (size_t)rbase * OUTF + n0 + cl) =
                make_float2(__low2float(r01), __high2float(r01));
            *(float2*)(Y + (size_t)(rbase + 8) * OUTF + n0 + cl) =
                make_float2(__low2float(r23), __high2float(r23));
        }
    }
}

extern "C" void kernel_launch(void* const* d_in, const int* in_sizes, int n_in,
                              void* d_out, int out_size) {
    const float* X  = (const float*)d_in[0];
    const int*   Wq = (const int*)d_in[1];
    const float* sc = (const float*)d_in[2];
    const float* bi = (const float*)d_in[3];
    float* Y = (float*)d_out;

    __half* Wh = nullptr;
    __half* Xh = nullptr;
    cudaGetSymbolAddress((void**)&Wh, g_Wh);
    cudaGetSymbolAddress((void**)&Xh, g_Xh);

    // Phase 1: dtype conversion (vectorized, exact-size grids)
    cvtW_kernel<<<(unsigned)((size_t)OUTF * INF / 4 / 256), 256>>>(
        (const int4*)Wq, (uint2*)Wh);
    cvtX_kernel<<<(unsigned)((size_t)MROWS * INF / 4 / 256), 256>>>(
        (const float4*)X, (uint2*)Xh);

    // Phase 2: GEMM
    static bool attr_done = false;
    if (!attr_done) {
        cudaFuncSetAttribute(w8lin_kernel,
                             cudaFuncAttributeMaxDynamicSharedMemorySize, SM_TOTAL);
        attr_done = true;
    }
    dim3 grid(OUTF / BN, MROWS / BM);   // (43, 64)
    w8lin_kernel<<<grid, THREADS, SM_TOTAL>>>(sc, bi, Y);
}

// round 8
// speedup vs baseline: 2.1582x; 1.0055x over previous
#include <cuda_runtime.h>
#include <cuda_fp16.h>
#include <cstdint>
#include <cstddef>

// ============================================================================
// W8Linear (harness dtypes: X f32, Wq i32, scale/bias f32, out f32).
//   Y = fp16( fp32(X @ W^T) * scale + bias ),  M=8192, K=4096, N=11008.
// Phase 1: convert W->fp16, X->fp16 into __device__ scratch.
// Phase 2: pipelined HMMA GEMM, M128 x N256 x K64 tiles, 256 thr (8 warps,
//          2x4, warp tile 64x64 -> B-fragment redundancy 2x instead of 4x),
//          4-stage cp.async ring, ldmatrix + mma.sync.m16n8k16, fp32 accum.
// ============================================================================

#define BM 128
#define BN 256
#define BK 64
#define KSTEPS 64
#define INF 4096
#define OUTF 11008
#define MROWS 8192
#define THREADS 256
#define STAGES 4

// SMEM layout (bytes)
#define ASTAGE 16384
#define BSTAGE 32768
#define SM_A  0
#define SM_B  (STAGES * ASTAGE)                   // 65536
#define SM_SC (SM_B + STAGES * BSTAGE)            // 196608
#define SM_BI (SM_SC + 512)
#define SM_TOTAL (SM_BI + 512)                    // 197632

// fp16 scratch (module-static device memory; not a runtime allocation)
__device__ __align__(16) __half g_Wh[(size_t)OUTF * INF];
__device__ __align__(16) __half g_Xh[(size_t)MROWS * INF];

__device__ __forceinline__ uint32_t swz(uint32_t o) { return o ^ ((o >> 3) & 0x70); }

__device__ __forceinline__ uint32_t s2u(const void* p) {
    return (uint32_t)__cvta_generic_to_shared(p);
}

__device__ __forceinline__ void cp16(uint32_t s, const void* g) {
    asm volatile("cp.async.cg.shared.global [%0], [%1], 16;" :: "r"(s), "l"(g));
}
#define CP_COMMIT() asm volatile("cp.async.commit_group;" ::: "memory")
#define CP_WAIT2()  asm volatile("cp.async.wait_group 2;" ::: "memory")

__device__ __forceinline__ void ldsm4(uint32_t (&r)[4], uint32_t a) {
    asm volatile("ldmatrix.sync.aligned.m8n8.x4.shared.b16 {%0,%1,%2,%3}, [%4];"
                 : "=r"(r[0]), "=r"(r[1]), "=r"(r[2]), "=r"(r[3]) : "r"(a));
}

__device__ __forceinline__ void mma16816(float (&d)[4], const uint32_t (&a)[4],
                                         uint32_t b0, uint32_t b1) {
    asm volatile("mma.sync.aligned.m16n8k16.row.col.f32.f16.f16.f32 "
                 "{%0,%1,%2,%3}, {%4,%5,%6,%7}, {%8,%9}, {%0,%1,%2,%3};"
                 : "+f"(d[0]), "+f"(d[1]), "+f"(d[2]), "+f"(d[3])
                 : "r"(a[0]), "r"(a[1]), "r"(a[2]), "r"(a[3]),
                   "r"(b0), "r"(b1));
}

__device__ __forceinline__ uint32_t h2u(__half2 h) {
    return *reinterpret_cast<uint32_t*>(&h);
}

// ---- Phase 1 kernels ----
__global__ void __launch_bounds__(256) cvtW_kernel(const int4* __restrict__ w,
                                                   uint2* __restrict__ o) {
    size_t i = (size_t)blockIdx.x * 256 + threadIdx.x;
    int4 v = w[i];
    uint2 r;
    r.x = h2u(__halves2half2(__int2half_rn(v.x), __int2half_rn(v.y)));
    r.y = h2u(__halves2half2(__int2half_rn(v.z), __int2half_rn(v.w)));
    o[i] = r;
}
__global__ void __launch_bounds__(256) cvtX_kernel(const float4* __restrict__ x,
                                                   uint2* __restrict__ o) {
    size_t i = (size_t)blockIdx.x * 256 + threadIdx.x;
    float4 v = x[i];
    uint2 r;
    r.x = h2u(__floats2half2_rn(v.x, v.y));
    r.y = h2u(__floats2half2_rn(v.z, v.w));
    o[i] = r;
}

// ---- Phase 2: GEMM ----
__global__ void __launch_bounds__(THREADS, 1)
w8lin_kernel(const float* __restrict__ scale, const float* __restrict__ bias,
             float* __restrict__ Y)
{
    extern __shared__ char smem[];
    const uint32_t sb = s2u(smem);
    const int tid = threadIdx.x;
    const int wid = tid >> 5;
    const int lid = tid & 31;
    const int n0 = blockIdx.x * BN;
    const int m0 = blockIdx.y * BM;
    const int m_off = (wid & 1) * 64;   // 2 M-warp groups (warp tile M64)
    const int n_off = (wid >> 1) * 64;  // 4 N-warp groups (warp tile N64)

    if (tid < 256) {
        ((__half*)(smem + SM_SC))[tid] = __float2half_rn(scale[n0 + tid]);
        ((__half*)(smem + SM_BI))[tid] = __float2half_rn(bias[n0 + tid]);
    }

    // ---- stage loaders (cp.async, SW128 rows of 128B) ----
    auto loadA = [&](int s, int stg) {
        uint32_t base = sb + SM_A + (uint32_t)stg * ASTAGE;
        const __half* g = g_Xh + (size_t)m0 * INF + (size_t)s * BK;
        #pragma unroll
        for (int i = 0; i < 4; i++) {
            int idx = tid + i * THREADS;          // 1024 16B chunks
            int r = idx >> 3, c = idx & 7;
            cp16(base + swz((uint32_t)(r * 128 + c * 16)),
                 g + (size_t)r * INF + c * 8);
        }
    };
    auto loadB = [&](int s, int stg) {
        uint32_t base = sb + SM_B + (uint32_t)stg * BSTAGE;
        const __half* g = g_Wh + (size_t)n0 * INF + (size_t)s * BK;
        #pragma unroll
        for (int i = 0; i < 8; i++) {
            int idx = tid + i * THREADS;          // 2048 16B chunks
            int r = idx >> 3, c = idx & 7;
            cp16(base + swz((uint32_t)(r * 128 + c * 16)),
                 g + (size_t)r * INF + c * 8);
        }
    };

    // ---- per-thread ldmatrix byte offsets (pre-swizzle; +kk*32 per k-step) ----
    uint32_t arow[4], brow[4];
    #pragma unroll
    for (int i = 0; i < 4; i++)
        arow[i] = (uint32_t)((m_off + i * 16 + (lid & 15)) * 128 + (lid >> 4) * 16);
    #pragma unroll
    for (int j = 0; j < 4; j++)
        brow[j] = (uint32_t)((n_off + j * 16 + ((lid >> 4) & 1) * 8 + (lid & 7)) * 128
                             + ((lid >> 3) & 1) * 16);

    float acc[4][8][4];
    #pragma unroll
    for (int i = 0; i < 4; i++)
        #pragma unroll
        for (int j = 0; j < 8; j++)
            #pragma unroll
            for (int q = 0; q < 4; q++) acc[i][j][q] = 0.0f;

    auto compute = [&](int stg) {
        uint32_t Ab = sb + SM_A + (uint32_t)stg * ASTAGE;
        uint32_t Bb = sb + SM_B + (uint32_t)stg * BSTAGE;
        #pragma unroll
        for (int kk = 0; kk < 4; kk++) {
            uint32_t a[4][4], b[4][4];
            #pragma unroll
            for (int i = 0; i < 4; i++) ldsm4(a[i], Ab + swz(arow[i] + kk * 32));
            #pragma unroll
            for (int j = 0; j < 4; j++) ldsm4(b[j], Bb + swz(brow[j] + kk * 32));
            #pragma unroll
            for (int i = 0; i < 4; i++)
                #pragma unroll
                for (int j = 0; j < 4; j++) {
                    mma16816(acc[i][2 * j],     a[i], b[j][0], b[j][1]);
                    mma16816(acc[i][2 * j + 1], a[i], b[j][2], b[j][3]);
                }
        }
    };

    // ---- prologue: fill 3 stages ----
    #pragma unroll
    for (int s = 0; s < 3; s++) {
        loadA(s, s); loadB(s, s); CP_COMMIT();
    }

    // ---- mainloop: one barrier per iter ----
    for (int s = 0; s < KSTEPS; s++) {
        CP_WAIT2();                 // my chunks of group s complete
        __syncthreads();            // -> all warps' chunks of stage s complete
        compute(s & 3);
        if (s + 3 < KSTEPS) {       // refill stage (s+3)&3 == (s-1)&3 (consumed)
            loadA(s + 3, (s + 3) & 3);
            loadB(s + 3, (s + 3) & 3);
        }
        CP_COMMIT();                // keep group accounting invariant
    }

    // ---- epilogue: fp32 acc -> fp16 round -> *scale + bias (fp16) -> f32 out ----
    const int gid = lid >> 2, tig = lid & 3;
    #pragma unroll
    for (int i = 0; i < 4; i++) {
        const int rbase = m0 + m_off + i * 16 + gid;
        #pragma unroll
        for (int j = 0; j < 8; j++) {
            const int cl = n_off + j * 8 + tig * 2;
            __half2 sc = *(const __half2*)(smem + SM_SC + cl * 2);
            __half2 bi = *(const __half2*)(smem + SM_BI + cl * 2);
            __half2 h01 = __floats2half2_rn(acc[i][j][0], acc[i][j][1]);
            __half2 h23 = __floats2half2_rn(acc[i][j][2], acc[i][j][3]);
            __half2 r01 = __hadd2(__hmul2(h01, sc), bi);
            __half2 r23 = __hadd2(__hmul2(h23, sc), bi);
            *(float2*)(Y + (size_t)rbase * OUTF + n0 + cl) =
                make_float2(__low2float(r01), __high2float(r01));
            *(float2*)(Y + (size_t)(rbase + 8) * OUTF + n0 + cl) =
                make_float2(__low2float(r23), __high2float(r23));
        }
    }
}

extern "C" void kernel_launch(void* const* d_in, const int* in_sizes, int n_in,
                              void* d_out, int out_size) {
    const float* X  = (const float*)d_in[0];
    const int*   Wq = (const int*)d_in[1];
    const float* sc = (const float*)d_in[2];
    const float* bi = (const float*)d_in[3];
    float* Y = (float*)d_out;

    __half* Wh = nullptr;
    __half* Xh = nullptr;
    cudaGetSymbolAddress((void**)&Wh, g_Wh);
    cudaGetSymbolAddress((void**)&Xh, g_Xh);

    // Phase 1: dtype conversion (vectorized, exact-size grids)
    cvtW_kernel<<<(unsigned)((size_t)OUTF * INF / 4 / 256), 256>>>(
        (const int4*)Wq, (uint2*)Wh);
    cvtX_kernel<<<(unsigned)((size_t)MROWS * INF / 4 / 256), 256>>>(
        (const float4*)X, (uint2*)Xh);

    // Phase 2: GEMM
    static bool attr_done = false;
    if (!attr_done) {
        cudaFuncSetAttribute(w8lin_kernel,
                             cudaFuncAttributeMaxDynamicSharedMemorySize, SM_TOTAL);
        attr_done = true;
    }
    dim3 grid(OUTF / BN, MROWS / BM);   // (43, 64)
    w8lin_kernel<<<grid, THREADS, SM_TOTAL>>>(sc, bi, Y);
}